// round 15
// baseline (speedup 1.0000x reference)
#include <cuda_runtime.h>
#include <cuda_bf16.h>
#include <math.h>
#include <stdint.h>

#define BB 4
#define LL 1024
#define DD 1024
#define NN 16
#define HH 64
#define RR 2048

// ---------------- scratch (static device globals: no allocations allowed) ---
__device__ float g_qh[BB*NN*LL*HH];   // [b][n][l][h] (tf32-rounded)
__device__ float g_cu[NN*RR + 128];   // c[n][j] = (rrb-rwb)[n] . r[n][j]
__device__ float g_o [BB*NN*LL*HH];   // attention output (tf32-rounded)
__device__ float g_x [BB*LL*DD];      // pre-layernorm residual sum

// bf16 attention operands (written by projection epilogues)
__device__ __nv_bfloat16 g_khb[BB*NN*LL*HH];  // [b][n][m][h]
__device__ __nv_bfloat16 g_vhb[BB*NN*LL*HH];
__device__ __nv_bfloat16 g_rb [NN*RR*HH];     // [n][j][h]

// tf32-rounded operand copies
__device__ float g_tq [BB*LL*DD];
__device__ float g_tk [BB*LL*DD];
__device__ float g_tv [BB*LL*DD];
__device__ float g_tpe[RR*DD];
__device__ float g_tqw[DD*NN*HH];
__device__ float g_tkw[DD*NN*HH];
__device__ float g_tvw[DD*NN*HH];
__device__ float g_trk[NN*DD*HH];
__device__ float g_tpw[NN*HH*DD];

// ---------------- helpers ---------------------------------------------------
__device__ __forceinline__ float tf32r(float x) {
    uint32_t u;
    asm("cvt.rna.tf32.f32 %0, %1;" : "=r"(u) : "f"(x));
    return __uint_as_float(u);
}
__device__ __forceinline__ float ex2f(float x) {
    float y;
    asm("ex2.approx.ftz.f32 %0, %1;" : "=f"(y) : "f"(x));
    return y;
}
// pack (lo=a, hi=b) into bf16x2
__device__ __forceinline__ uint32_t bf2(float a, float b) {
    uint32_t r;
    asm("cvt.rn.bf16x2.f32 %0, %1, %2;" : "=r"(r) : "f"(b), "f"(a));
    return r;
}
__device__ __forceinline__ void cpa16(uint32_t dst, const void* src) {
    asm volatile("cp.async.cg.shared.global [%0], [%1], 16;\n" :: "r"(dst), "l"(src));
}

__device__ __forceinline__ void mma_tf32(float* d, const uint32_t* a, const uint32_t* b) {
    asm volatile(
        "mma.sync.aligned.m16n8k8.row.col.f32.tf32.tf32.f32 "
        "{%0,%1,%2,%3}, {%4,%5,%6,%7}, {%8,%9}, {%0,%1,%2,%3};\n"
        : "+f"(d[0]), "+f"(d[1]), "+f"(d[2]), "+f"(d[3])
        : "r"(a[0]), "r"(a[1]), "r"(a[2]), "r"(a[3]), "r"(b[0]), "r"(b[1]));
}
__device__ __forceinline__ void mma_bf16(float* d, const uint32_t* a, const uint32_t* b) {
    asm volatile(
        "mma.sync.aligned.m16n8k16.row.col.f32.bf16.bf16.f32 "
        "{%0,%1,%2,%3}, {%4,%5,%6,%7}, {%8,%9}, {%0,%1,%2,%3};\n"
        : "+f"(d[0]), "+f"(d[1]), "+f"(d[2]), "+f"(d[3])
        : "r"(a[0]), "r"(a[1]), "r"(a[2]), "r"(a[3]), "r"(b[0]), "r"(b[1]));
}
__device__ __forceinline__ void ldsm_x4(uint32_t& r0, uint32_t& r1, uint32_t& r2, uint32_t& r3, uint32_t addr) {
    asm volatile("ldmatrix.sync.aligned.m8n8.x4.shared.b16 {%0,%1,%2,%3}, [%4];"
                 : "=r"(r0), "=r"(r1), "=r"(r2), "=r"(r3) : "r"(addr));
}
__device__ __forceinline__ void ldsm_x4t(uint32_t& r0, uint32_t& r1, uint32_t& r2, uint32_t& r3, uint32_t addr) {
    asm volatile("ldmatrix.sync.aligned.m8n8.x4.trans.shared.b16 {%0,%1,%2,%3}, [%4];"
                 : "=r"(r0), "=r"(r1), "=r"(r2), "=r"(r3) : "r"(addr));
}

// ---------------- fused tf32 rounding pass (all GEMM operands) --------------
struct R9 {
    const float* in[9];
    float*       out[9];
    int          n[9];
};

__global__ __launch_bounds__(256)
void roundk(R9 r)
{
    const int seg = blockIdx.y;
    const float* in  = r.in[seg];
    float*       out = r.out[seg];
    const int n = r.n[seg];
    for (int i = (blockIdx.x*256 + threadIdx.x)*4; i < n; i += gridDim.x*256*4) {
        float4 v = *reinterpret_cast<const float4*>(in + i);
        v.x = tf32r(v.x); v.y = tf32r(v.y); v.z = tf32r(v.z); v.w = tf32r(v.w);
        *reinterpret_cast<float4*>(out + i) = v;
    }
}

// ---------------- c_u precompute: g_cu[n][j] = (rrb-rwb)[n] . r[n][j] -------
__global__ __launch_bounds__(256)
void cu_kernel(const float* __restrict__ rwb, const float* __restrict__ rrb)
{
    const int idx = blockIdx.x*256 + threadIdx.x;   // 32768 total
    const int n = idx >> 11;
    const int j = idx & 2047;
    const __nv_bfloat16* rr = g_rb + ((long)n*RR + j)*HH;
    const float* dw = rwb + n*64;
    const float* dr = rrb + n*64;
    float acc = 0.f;
    #pragma unroll
    for (int h = 0; h < 64; h++)
        acc += (dr[h]-dw[h]) * __bfloat162float(rr[h]);
    g_cu[idx] = acc;
}

// ---------------- tf32 tensor-core GEMM machinery (2-stage pipeline) --------
struct GemmArgs {
    const float* A;
    const float* W;
    const float* bias;
    const float* resid;
    float*       C;
};

#define AS_STRIDE 36
#define BS_STRIDE 136
#define AS_FLOATS (128*AS_STRIDE)
#define BS_FLOATS (32*BS_STRIDE)
#define GEMM_SMEM ((2*AS_FLOATS + 2*BS_FLOATS)*4)   // 71680 bytes

// runtime-mode stage copy (A row-major; B: rpos picks r_kernel gather)
__device__ __forceinline__ void stage_copy_rt(
    const float* __restrict__ A, const float* __restrict__ W, bool rpos,
    uint32_t asB, uint32_t bsB, int row0, int col0, int k0, int tid)
{
    #pragma unroll
    for (int i = 0; i < 4; i++) {
        const int c = tid + i*256;
        const int arow = c >> 3, akc = (c & 7) * 4;
        const float* srcA = A + (long)(row0 + arow)*1024 + k0 + akc;
        asm volatile("cp.async.cg.shared.global [%0], [%1], 16;\n"
                     :: "r"(asB + (uint32_t)((arow*AS_STRIDE + akc)*4)), "l"(srcA));
        const int bk = c >> 5, bnc = (c & 31) * 4;
        const float* srcB;
        if (rpos) {
            const int col = col0 + bnc;
            srcB = W + (long)(col >> 6)*(DD*HH) + (long)(k0 + bk)*HH + (col & 63);
        } else {
            srcB = W + (long)(k0 + bk)*1024 + col0 + bnc;
        }
        asm volatile("cp.async.cg.shared.global [%0], [%1], 16;\n"
                     :: "r"(bsB + (uint32_t)((bk*BS_STRIDE + bnc)*4)), "l"(srcB));
    }
    asm volatile("cp.async.commit_group;\n");
}

// merged q/k/v projections + rpos in one launch (grid.z = 0..3)
// epilogues: z=0 -> g_qh f32; z=1 -> g_khb bf16; z=2 -> g_vhb bf16; z=3 -> g_rb bf16
__global__ __launch_bounds__(256, 2)
void gemm_qkvr(GemmArgs g0, GemmArgs g1, GemmArgs g2, GemmArgs g3)
{
    const int z = blockIdx.z;
    const bool rpos = (z == 3);
    if (rpos && blockIdx.y >= 16) return;
    const GemmArgs ga = (z==0)?g0 : (z==1)?g1 : (z==2)?g2 : g3;

    extern __shared__ float smem[];
    float* As = smem;
    float* Bs = smem + 2*AS_FLOATS;

    const int tid  = threadIdx.x;
    const int lane = tid & 31;
    const int w    = tid >> 5;
    const int wm   = w & 1;
    const int wn   = w >> 1;
    const int row0 = blockIdx.y * 128;
    const int col0 = blockIdx.x * 128;

    const uint32_t asB = (uint32_t)__cvta_generic_to_shared(As);
    const uint32_t bsB = (uint32_t)__cvta_generic_to_shared(Bs);

    float acc[4][4][4];
    #pragma unroll
    for (int i = 0; i < 4; i++)
        #pragma unroll
        for (int j = 0; j < 4; j++)
            #pragma unroll
            for (int q = 0; q < 4; q++) acc[i][j][q] = 0.f;

    stage_copy_rt(ga.A, ga.W, rpos, asB, bsB, row0, col0, 0, tid);

    const int NIT = 1024/32;
    for (int it = 0; it < NIT; it++) {
        const int s = it & 1;
        if (it + 1 < NIT) {
            stage_copy_rt(ga.A, ga.W, rpos,
                          asB + (uint32_t)((s^1)*AS_FLOATS*4),
                          bsB + (uint32_t)((s^1)*BS_FLOATS*4),
                          row0, col0, (it+1)*32, tid);
            asm volatile("cp.async.wait_group 1;\n");
        } else {
            asm volatile("cp.async.wait_group 0;\n");
        }
        __syncthreads();

        const float* as = As + s*AS_FLOATS;
        const float* bs = Bs + s*BS_FLOATS;
        #pragma unroll
        for (int k8 = 0; k8 < 32; k8 += 8) {
            uint32_t af[4][4], bf[4][2];
            const int fr = lane >> 2;
            const int fc = lane & 3;
            #pragma unroll
            for (int im = 0; im < 4; im++) {
                const int r = wm*64 + im*16 + fr;
                const int c = k8 + fc;
                af[im][0] = __float_as_uint(as[r*AS_STRIDE + c]);
                af[im][1] = __float_as_uint(as[(r+8)*AS_STRIDE + c]);
                af[im][2] = __float_as_uint(as[r*AS_STRIDE + c + 4]);
                af[im][3] = __float_as_uint(as[(r+8)*AS_STRIDE + c + 4]);
            }
            #pragma unroll
            for (int jn = 0; jn < 4; jn++) {
                const int nn = wn*32 + jn*8 + fr;
                const int kk = k8 + fc;
                bf[jn][0] = __float_as_uint(bs[kk*BS_STRIDE + nn]);
                bf[jn][1] = __float_as_uint(bs[(kk+4)*BS_STRIDE + nn]);
            }
            #pragma unroll
            for (int im = 0; im < 4; im++)
                #pragma unroll
                for (int jn = 0; jn < 4; jn++)
                    mma_tf32(acc[im][jn], af[im], bf[jn]);
        }
        __syncthreads();
    }

    const int fr = lane >> 2;
    const int fc = lane & 3;
    #pragma unroll
    for (int jn = 0; jn < 4; jn++) {
        const int colp = col0 + wn*32 + jn*8 + fc*2;
        float b0 = 0.f, b1 = 0.f;
        if (!rpos && ga.bias != nullptr) {
            b0 = ga.bias[colp]; b1 = ga.bias[colp + 1];
        }
        #pragma unroll
        for (int im = 0; im < 4; im++) {
            #pragma unroll
            for (int half = 0; half < 2; half++) {
                const int row = row0 + wm*64 + im*16 + fr + half*8;
                float v0 = acc[im][jn][half*2 + 0] + b0;
                float v1 = acc[im][jn][half*2 + 1] + b1;
                if (rpos) {
                    long o = (long)(colp >> 6)*(RR*HH) + (long)row*HH + (colp & 63);
                    *reinterpret_cast<uint32_t*>(g_rb + o) = bf2(v0, v1);
                } else {
                    long o = (long)((row >> 10)*NN + (colp >> 6))*(LL*HH)
                           + (long)(row & 1023)*HH + (colp & 63);
                    if (z == 0)
                        *reinterpret_cast<float2*>(g_qh + o) = make_float2(tf32r(v0), tf32r(v1));
                    else if (z == 1)
                        *reinterpret_cast<uint32_t*>(g_khb + o) = bf2(v0, v1);
                    else
                        *reinterpret_cast<uint32_t*>(g_vhb + o) = bf2(v0, v1);
                }
            }
        }
    }
}

// POST gemm: A = g_o gather, row-major W, +bias +resid (2-stage)
__device__ __forceinline__ void stage_copy_post(
    const float* __restrict__ A, const float* __restrict__ W,
    uint32_t asB, uint32_t bsB, int row0, int col0, int k0, int tid)
{
    #pragma unroll
    for (int i = 0; i < 4; i++) {
        const int c = tid + i*256;
        const int arow = c >> 3, akc = (c & 7) * 4;
        const int row = row0 + arow, k = k0 + akc;
        const float* srcA = A + (long)(row >> 10)*(NN*LL*HH) + (long)(k >> 6)*(LL*HH)
                              + (long)(row & 1023)*HH + (k & 63);
        asm volatile("cp.async.cg.shared.global [%0], [%1], 16;\n"
                     :: "r"(asB + (uint32_t)((arow*AS_STRIDE + akc)*4)), "l"(srcA));
        const int bk = c >> 5, bnc = (c & 31) * 4;
        const float* srcB = W + (long)(k0 + bk)*1024 + col0 + bnc;
        asm volatile("cp.async.cg.shared.global [%0], [%1], 16;\n"
                     :: "r"(bsB + (uint32_t)((bk*BS_STRIDE + bnc)*4)), "l"(srcB));
    }
    asm volatile("cp.async.commit_group;\n");
}

__global__ __launch_bounds__(256, 2)
void gemm_post(GemmArgs ga)
{
    extern __shared__ float smem[];
    float* As = smem;
    float* Bs = smem + 2*AS_FLOATS;

    const int tid  = threadIdx.x;
    const int lane = tid & 31;
    const int w    = tid >> 5;
    const int wm   = w & 1;
    const int wn   = w >> 1;
    const int row0 = blockIdx.y * 128;
    const int col0 = blockIdx.x * 128;

    const uint32_t asB = (uint32_t)__cvta_generic_to_shared(As);
    const uint32_t bsB = (uint32_t)__cvta_generic_to_shared(Bs);

    float acc[4][4][4];
    #pragma unroll
    for (int i = 0; i < 4; i++)
        #pragma unroll
        for (int j = 0; j < 4; j++)
            #pragma unroll
            for (int q = 0; q < 4; q++) acc[i][j][q] = 0.f;

    stage_copy_post(ga.A, ga.W, asB, bsB, row0, col0, 0, tid);

    const int NIT = 1024/32;
    for (int it = 0; it < NIT; it++) {
        const int s = it & 1;
        if (it + 1 < NIT) {
            stage_copy_post(ga.A, ga.W,
                            asB + (uint32_t)((s^1)*AS_FLOATS*4),
                            bsB + (uint32_t)((s^1)*BS_FLOATS*4),
                            row0, col0, (it+1)*32, tid);
            asm volatile("cp.async.wait_group 1;\n");
        } else {
            asm volatile("cp.async.wait_group 0;\n");
        }
        __syncthreads();

        const float* as = As + s*AS_FLOATS;
        const float* bs = Bs + s*BS_FLOATS;
        #pragma unroll
        for (int k8 = 0; k8 < 32; k8 += 8) {
            uint32_t af[4][4], bf[4][2];
            const int fr = lane >> 2;
            const int fc = lane & 3;
            #pragma unroll
            for (int im = 0; im < 4; im++) {
                const int r = wm*64 + im*16 + fr;
                const int c = k8 + fc;
                af[im][0] = __float_as_uint(as[r*AS_STRIDE + c]);
                af[im][1] = __float_as_uint(as[(r+8)*AS_STRIDE + c]);
                af[im][2] = __float_as_uint(as[r*AS_STRIDE + c + 4]);
                af[im][3] = __float_as_uint(as[(r+8)*AS_STRIDE + c + 4]);
            }
            #pragma unroll
            for (int jn = 0; jn < 4; jn++) {
                const int nn = wn*32 + jn*8 + fr;
                const int kk = k8 + fc;
                bf[jn][0] = __float_as_uint(bs[kk*BS_STRIDE + nn]);
                bf[jn][1] = __float_as_uint(bs[(kk+4)*BS_STRIDE + nn]);
            }
            #pragma unroll
            for (int im = 0; im < 4; im++)
                #pragma unroll
                for (int jn = 0; jn < 4; jn++)
                    mma_tf32(acc[im][jn], af[im], bf[jn]);
        }
        __syncthreads();
    }

    const int fr = lane >> 2;
    const int fc = lane & 3;
    #pragma unroll
    for (int jn = 0; jn < 4; jn++) {
        const int colp = col0 + wn*32 + jn*8 + fc*2;
        float b0 = ga.bias[colp], b1 = ga.bias[colp + 1];
        #pragma unroll
        for (int im = 0; im < 4; im++) {
            #pragma unroll
            for (int half = 0; half < 2; half++) {
                const int row = row0 + wm*64 + im*16 + fr + half*8;
                float v0 = acc[im][jn][half*2 + 0] + b0;
                float v1 = acc[im][jn][half*2 + 1] + b1;
                long o = (long)row*1024 + colp;
                float2 rr = *reinterpret_cast<const float2*>(ga.resid + o);
                *reinterpret_cast<float2*>(ga.C + o) = make_float2(v0 + rr.x, v1 + rr.y);
            }
        }
    }
}

// ---------------- fused attention: bf16 mma + ldmatrix, double-buffered -----
// smem byte layout (144-byte strides, conflict-free ldmatrix phases):
//   QW  [64][72]  bf16            @ 0      (9216)
//   KT0/RB0/VS0                   @ 9216 / 18432 / 36864
//   KT1/RB1/VS1                   @ 46080 / 55296 / 73728   (buf stride 36864)
//   G2s [64][132] bf16 [l][u]     @ 82944  (16896)  Ps[64][72] bf16 union
//   maskv @ 99840, rmaxs @ 100096, rsums @ 100608, cu @ 101120
#define QW_OFF   0
#define KT_OFF   9216
#define RB_OFF   18432
#define VS_OFF   36864
#define BUF_STR  36864
#define G2_OFF   82944
#define PS_OFF   82944
#define MK_OFF   99840
#define RM_OFF   100096
#define RS_OFF   100608
#define CU_OFF   101120
#define ATT_SMEM 101632
#define SC_LOG2 0.18033688011112042f   // 0.125 * log2(e)
#define MASK_LOG2 -1442695.04f         // -1e6 * log2(e)

__global__ __launch_bounds__(256, 2)
void attn_mma(const int* __restrict__ padding,
              const float* __restrict__ rwb)
{
    extern __shared__ char smB[];
    const uint32_t s0 = (uint32_t)__cvta_generic_to_shared(smB);
    __nv_bfloat16* G2b = reinterpret_cast<__nv_bfloat16*>(smB + G2_OFF);
    float* maskv = reinterpret_cast<float*>(smB + MK_OFF);
    float* rmaxs = reinterpret_cast<float*>(smB + RM_OFF);
    float* rsums = reinterpret_cast<float*>(smB + RS_OFF);
    float* cu_s  = reinterpret_cast<float*>(smB + CU_OFF);

    const int tid  = threadIdx.x;
    const int lane = tid & 31;
    const int w    = tid >> 5;
    const int wr   = w >> 1;                  // 0..3
    const int wc   = w & 1;                   // 0..1
    const int fr   = lane >> 2;               // 0..7
    const int fc   = lane & 3;                // 0..3
    const int bn   = blockIdx.y;
    const int l0   = blockIdx.x * 64;
    const int b    = bn >> 4;
    const int n    = bn & 15;

    const float* qh = g_qh + (long)bn * (LL*HH);
    const __nv_bfloat16* khb = g_khb + (long)bn * (LL*HH);
    const __nv_bfloat16* vhb = g_vhb + (long)bn * (LL*HH);
    const __nv_bfloat16* rbp = g_rb  + (long)n  * (RR*HH);
    const float* cp = g_cu + (long)n  * RR;
    float*       op = g_o  + (long)bn * (LL*HH);

    // ---- prologue: QW = bf16(q + rwb); zero RB row 127 (both buffers)
    #pragma unroll
    for (int i = 0; i < 4; i++) {
        const int idx = tid + i*256;
        const int l = idx >> 4, hc = (idx & 15)*4;
        float4 v = *reinterpret_cast<const float4*>(qh + (long)(l0 + l)*64 + hc);
        float bw0 = rwb[n*64 + hc + 0], bw1 = rwb[n*64 + hc + 1];
        float bw2 = rwb[n*64 + hc + 2], bw3 = rwb[n*64 + hc + 3];
        *reinterpret_cast<uint2*>(smB + QW_OFF + l*144 + hc*2) =
            make_uint2(bf2(v.x + bw0, v.y + bw1), bf2(v.z + bw2, v.w + bw3));
    }
    if (tid < 36) {
        reinterpret_cast<float*>(smB + RB_OFF + 127*144)[tid] = 0.f;
        reinterpret_cast<float*>(smB + RB_OFF + BUF_STR + 127*144)[tid] = 0.f;
    }

    // ---- stage tile 0 into buffer 0; mask/cu for tile 0
    {
        const int jmin0 = LL - l0 - 63;
        #pragma unroll
        for (int i = 0; i < 2; i++) {
            const int idx = tid + i*256;
            const int row = idx >> 3, c = (idx & 7)*8;
            cpa16(s0 + KT_OFF + row*144 + c*2, khb + (long)row*64 + c);
        }
        #pragma unroll
        for (int i = 0; i < 4; i++) {
            const int idx = tid + i*256;
            if (idx < 1016) {
                const int row = idx >> 3, c = (idx & 7)*8;
                cpa16(s0 + RB_OFF + row*144 + c*2, rbp + (long)(jmin0 + row)*64 + c);
            }
        }
        #pragma unroll
        for (int i = 0; i < 2; i++) {
            const int idx = tid + i*256;
            const int row = idx >> 3, c = (idx & 7)*8;
            cpa16(s0 + VS_OFF + row*144 + c*2, vhb + (long)row*64 + c);
        }
        asm volatile("cp.async.commit_group;\n");
        if (tid < 64)
            maskv[tid] = (padding[b*LL + tid] != 0) ? MASK_LOG2 : 0.0f;
        if (tid < 128)
            cu_s[tid] = cp[jmin0 + tid];
    }

    // lane-static ldmatrix address components
    const int gA   = lane >> 3;
    const int rA   = lane & 7;
    const int rowA = wr*16 + (gA & 1)*8 + rA;
    const int colA = (gA >> 1)*8;
    const uint32_t aQW = s0 + QW_OFF + rowA*144 + colA*2;
    const uint32_t aPS = s0 + PS_OFF + rowA*144 + colA*2;
    const int nsel = (lane & 7) + ((lane & 16) >> 1);   // B x4: n offset
    const int ksel = (lane & 8);                        // B x4: k offset
    const int tsel = (lane & 15);                       // B x4t: k row
    const int csel = ((lane & 16) >> 1);                // B x4t: col offset

    float O[4][4];
    float mi[2], li[2];
    #pragma unroll
    for (int jn = 0; jn < 4; jn++)
        #pragma unroll
        for (int q = 0; q < 4; q++) O[jn][q] = 0.f;
    mi[0] = mi[1] = -1e30f;
    li[0] = li[1] = 0.f;

    for (int t = 0; t < 16; t++) {
        const int m0  = t*64;
        const uint32_t bo  = (uint32_t)((t & 1) * BUF_STR);
        const uint32_t bon = (uint32_t)(((t + 1) & 1) * BUF_STR);
        const int jmin = LL + m0 - l0 - 63;

        __syncthreads();   // (A) prior tile's reads of target buffer all done
        asm volatile("cp.async.wait_group 0;\n");   // tile t data landed

        // ---- issue staging for tile t+1 into alternate buffer
        if (t + 1 < 16) {
            const int m0n = m0 + 64;
            #pragma unroll
            for (int i = 0; i < 2; i++) {
                const int idx = tid + i*256;
                const int row = idx >> 3, c = (idx & 7)*8;
                cpa16(s0 + KT_OFF + bon + row*144 + c*2, khb + (long)(m0n + row)*64 + c);
            }
            #pragma unroll
            for (int i = 0; i < 4; i++) {
                const int idx = tid + i*256;
                if (idx < 1016) {
                    const int row = idx >> 3, c = (idx & 7)*8;
                    cpa16(s0 + RB_OFF + bon + row*144 + c*2,
                          rbp + (long)(jmin + 64 + row)*64 + c);
                }
            }
            #pragma unroll
            for (int i = 0; i < 2; i++) {
                const int idx = tid + i*256;
                const int row = idx >> 3, c = (idx & 7)*8;
                cpa16(s0 + VS_OFF + bon + row*144 + c*2, vhb + (long)(m0n + row)*64 + c);
            }
            asm volatile("cp.async.commit_group;\n");
        }

        // prefetch next tile's mask/cu into registers (LDG latency hidden)
        float pm = 0.f, pc = 0.f;
        if (t + 1 < 16) {
            if (tid < 64)
                pm = (padding[b*LL + m0 + 64 + tid] != 0) ? MASK_LOG2 : 0.0f;
            if (tid < 128)
                pc = cp[jmin + 64 + tid];
        }

        __syncthreads();   // (B) tile t smem (incl. prior-iter mask/cu STS) visible

        // ---- loop1: G1 (s1) + G2 first half, single A per k-chunk
        float s1[4][4], g2[4][4];
        #pragma unroll
        for (int jn = 0; jn < 4; jn++)
            #pragma unroll
            for (int q = 0; q < 4; q++) { s1[jn][q] = 0.f; g2[jn][q] = 0.f; }
        #pragma unroll
        for (int k0 = 0; k0 < 64; k0 += 16) {
            uint32_t a[4];
            ldsm_x4(a[0], a[1], a[2], a[3], aQW + k0*2);
            #pragma unroll
            for (int p = 0; p < 2; p++) {
                uint32_t b4[4];
                ldsm_x4(b4[0], b4[1], b4[2], b4[3],
                        s0 + KT_OFF + bo + (wc*32 + p*16 + nsel)*144 + (k0 + ksel)*2);
                mma_bf16(s1[p*2],   a, b4);
                mma_bf16(s1[p*2+1], a, b4 + 2);
            }
            #pragma unroll
            for (int p = 0; p < 2; p++) {
                uint32_t b4[4];
                ldsm_x4(b4[0], b4[1], b4[2], b4[3],
                        s0 + RB_OFF + bo + (wc*64 + p*16 + nsel)*144 + (k0 + ksel)*2);
                mma_bf16(g2[p*2],   a, b4);
                mma_bf16(g2[p*2+1], a, b4 + 2);
            }
        }
        // spill g2 half A (+cu) -> G2b[l][u] (bf16)
        {
            const int lb = (wr*16 + fr)*132;
            #pragma unroll
            for (int jn = 0; jn < 4; jn++) {
                const int ub = wc*64 + jn*8 + fc*2;
                float2 cc = *reinterpret_cast<const float2*>(&cu_s[ub]);
                *reinterpret_cast<uint32_t*>(smB + G2_OFF + (lb + ub)*2) =
                    bf2(g2[jn][0] + cc.x, g2[jn][1] + cc.y);
                *reinterpret_cast<uint32_t*>(smB + G2_OFF + (lb + 8*132 + ub)*2) =
                    bf2(g2[jn][2] + cc.x, g2[jn][3] + cc.y);
            }
        }
        // ---- loop2: G2 second half
        #pragma unroll
        for (int jn = 0; jn < 4; jn++)
            #pragma unroll
            for (int q = 0; q < 4; q++) g2[jn][q] = 0.f;
        #pragma unroll
        for (int k0 = 0; k0 < 64; k0 += 16) {
            uint32_t a[4];
            ldsm_x4(a[0], a[1], a[2], a[3], aQW + k0*2);
            #pragma unroll
            for (int p = 0; p < 2; p++) {
                uint32_t b4[4];
                ldsm_x4(b4[0], b4[1], b4[2], b4[3],
                        s0 + RB_OFF + bo + (wc*64 + 32 + p*16 + nsel)*144 + (k0 + ksel)*2);
                mma_bf16(g2[p*2],   a, b4);
                mma_bf16(g2[p*2+1], a, b4 + 2);
            }
        }
        {
            const int lb = (wr*16 + fr)*132;
            #pragma unroll
            for (int jn = 0; jn < 4; jn++) {
                const int ub = wc*64 + 32 + jn*8 + fc*2;
                float2 cc = *reinterpret_cast<const float2*>(&cu_s[ub]);
                *reinterpret_cast<uint32_t*>(smB + G2_OFF + (lb + ub)*2) =
                    bf2(g2[jn][0] + cc.x, g2[jn][1] + cc.y);
                *reinterpret_cast<uint32_t*>(smB + G2_OFF + (lb + 8*132 + ub)*2) =
                    bf2(g2[jn][2] + cc.x, g2[jn][3] + cc.y);
            }
        }
        __syncthreads();   // (C) G2b complete; cu_s reads done

        // ---- diagonal gather + row max
        float sv[4][4];
        float rmx[2] = {-1e30f, -1e30f};
        #pragma unroll
        for (int jn = 0; jn < 4; jn++) {
            #pragma unroll
            for (int q = 0; q < 4; q++) {
                const int ll = wr*16 + fr + (q >> 1)*8;
                const int mc = wc*32 + jn*8 + fc*2 + (q & 1);
                const int u  = mc - ll + 63;
                float x = (s1[jn][q] + __bfloat162float(G2b[ll*132 + u])) * SC_LOG2
                        + maskv[mc];
                sv[jn][q] = x;
                rmx[q >> 1] = fmaxf(rmx[q >> 1], x);
            }
        }
        #pragma unroll
        for (int r = 0; r < 2; r++) {
            rmx[r] = fmaxf(rmx[r], __shfl_xor_sync(0xffffffffu, rmx[r], 1));
            rmx[r] = fmaxf(rmx[r], __shfl_xor_sync(0xffffffffu, rmx[r], 2));
        }
        if (fc == 0) {
            rmaxs[wc*64 + wr*16 + fr]     = rmx[0];
            rmaxs[wc*64 + wr*16 + fr + 8] = rmx[1];
        }
        __syncthreads();   // (D) row maxes ready; maskv/cu_s reads all done

        // ---- store next tile's mask/cu (reads for tile t finished at (D))
        if (t + 1 < 16) {
            if (tid < 64)  maskv[tid] = pm;
            if (tid < 128) cu_s[tid]  = pc;
        }

        // ---- softmax: exp2, P store (bf16), partial sums
        float nm[2], al[2], psum[2];
        #pragma unroll
        for (int r = 0; r < 2; r++) {
            const int row = wr*16 + fr + r*8;
            const float tm = fmaxf(rmaxs[row], rmaxs[64 + row]);
            nm[r] = fmaxf(mi[r], tm);
            al[r] = ex2f(mi[r] - nm[r]);
            mi[r] = nm[r];
            psum[r] = 0.f;
        }
        #pragma unroll
        for (int jn = 0; jn < 4; jn++) {
            #pragma unroll
            for (int r = 0; r < 2; r++) {
                float p0 = ex2f(sv[jn][r*2 + 0] - nm[r]);
                float p1 = ex2f(sv[jn][r*2 + 1] - nm[r]);
                psum[r] += p0 + p1;
                const int ll = wr*16 + fr + r*8;
                const int mc = wc*32 + jn*8 + fc*2;
                *reinterpret_cast<uint32_t*>(smB + PS_OFF + ll*144 + mc*2) = bf2(p0, p1);
            }
        }
        #pragma unroll
        for (int r = 0; r < 2; r++) {
            psum[r] += __shfl_xor_sync(0xffffffffu, psum[r], 1);
            psum[r] += __shfl_xor_sync(0xffffffffu, psum[r], 2);
        }
        if (fc == 0) {
            rsums[wc*64 + wr*16 + fr]     = psum[0];
            rsums[wc*64 + wr*16 + fr + 8] = psum[1];
        }
        __syncthreads();   // (E) Ps + rsums ready (VS staged with tile t group)

        // ---- li update, O rescale, PV mma
        #pragma unroll
        for (int r = 0; r < 2; r++) {
            const int row = wr*16 + fr + r*8;
            li[r] = li[r]*al[r] + (rsums[row] + rsums[64 + row]);
        }
        #pragma unroll
        for (int jn = 0; jn < 4; jn++) {
            O[jn][0] *= al[0]; O[jn][1] *= al[0];
            O[jn][2] *= al[1]; O[jn][3] *= al[1];
        }
        #pragma unroll
        for (int k0 = 0; k0 < 64; k0 += 16) {
            uint32_t a[4];
            ldsm_x4(a[0], a[1], a[2], a[3], aPS + k0*2);
            #pragma unroll
            for (int p = 0; p < 2; p++) {
                uint32_t b4[4];
                ldsm_x4t(b4[0], b4[1], b4[2], b4[3],
                         s0 + VS_OFF + bo + (k0 + tsel)*144 + (wc*32 + p*16 + csel)*2);
                mma_bf16(O[p*2],   a, b4);
                mma_bf16(O[p*2+1], a, b4 + 2);
            }
        }
    }

    // ---- final: normalize, round (feeds tf32 POST GEMM), write
    const float inv0 = 1.0f / li[0];
    const float inv1 = 1.0f / li[1];
    #pragma unroll
    for (int jn = 0; jn < 4; jn++) {
        const int col = wc*32 + jn*8 + fc*2;
        const int lr0 = l0 + wr*16 + fr;
        *reinterpret_cast<float2*>(op + (long)lr0*64 + col) =
            make_float2(tf32r(O[jn][0]*inv0), tf32r(O[jn][1]*inv0));
        *reinterpret_cast<float2*>(op + (long)(lr0 + 8)*64 + col) =
            make_float2(tf32r(O[jn][2]*inv1), tf32r(O[jn][3]*inv1));
    }
}

// ---------------- layernorm over D per (b,l) row (shuffle reduce) -----------
__global__ __launch_bounds__(256)
void ln_kernel(const float* __restrict__ lng, const float* __restrict__ lnb,
               float* __restrict__ out)
{
    __shared__ float part[8];
    __shared__ float bcast;
    const int row = blockIdx.x;
    const int tid = threadIdx.x;
    const int lane = tid & 31;
    const int wid = tid >> 5;
    const float* x = g_x + (long)row * DD;

    float4 v = reinterpret_cast<const float4*>(x)[tid];
    float s = v.x + v.y + v.z + v.w;
    #pragma unroll
    for (int off = 16; off > 0; off >>= 1)
        s += __shfl_xor_sync(0xffffffffu, s, off);
    if (lane == 0) part[wid] = s;
    __syncthreads();
    if (tid == 0) {
        float t = 0.f;
        #pragma unroll
        for (int i = 0; i < 8; i++) t += part[i];
        bcast = t * (1.f / DD);
    }
    __syncthreads();
    const float mu = bcast;

    float dx = v.x - mu, dy = v.y - mu, dz = v.z - mu, dw = v.w - mu;
    float vs = dx*dx + dy*dy + dz*dz + dw*dw;
    #pragma unroll
    for (int off = 16; off > 0; off >>= 1)
        vs += __shfl_xor_sync(0xffffffffu, vs, off);
    if (lane == 0) part[wid] = vs;
    __syncthreads();
    if (tid == 0) {
        float t = 0.f;
        #pragma unroll
        for (int i = 0; i < 8; i++) t += part[i];
        bcast = rsqrtf(t * (1.f / DD) + 1e-5f);
    }
    __syncthreads();
    const float inv = bcast;

    float4 g = reinterpret_cast<const float4*>(lng)[tid];
    float4 be = reinterpret_cast<const float4*>(lnb)[tid];
    float4 o;
    o.x = dx * inv * g.x + be.x;
    o.y = dy * inv * g.y + be.y;
    o.z = dz * inv * g.z + be.z;
    o.w = dw * inv * g.w + be.w;
    reinterpret_cast<float4*>(out + (long)row*DD)[tid] = o;
}

// ---------------- launcher ---------------------------------------------------
extern "C" void kernel_launch(void* const* d_in, const int* in_sizes, int n_in,
                              void* d_out, int out_size)
{
    const float* q   = (const float*)d_in[0];
    const float* k   = (const float*)d_in[1];
    const float* v   = (const float*)d_in[2];
    const float* pe  = (const float*)d_in[3];
    const int*   pad = (const int*)d_in[4];
    const float* q_w = (const float*)d_in[5];
    const float* k_w = (const float*)d_in[6];
    const float* k_b = (const float*)d_in[7];
    const float* v_w = (const float*)d_in[8];
    const float* v_b = (const float*)d_in[9];
    const float* rwb = (const float*)d_in[10];
    const float* rrb = (const float*)d_in[11];
    const float* rk  = (const float*)d_in[12];
    const float* pw  = (const float*)d_in[13];
    const float* pb  = (const float*)d_in[14];
    const float* lng = (const float*)d_in[15];
    const float* lnb = (const float*)d_in[16];

    void *p_o, *p_x;
    void *p_tq, *p_tk, *p_tv, *p_tpe, *p_tqw, *p_tkw, *p_tvw, *p_trk, *p_tpw;
    cudaGetSymbolAddress(&p_o,  g_o);
    cudaGetSymbolAddress(&p_x,  g_x);
    cudaGetSymbolAddress(&p_tq,  g_tq);
    cudaGetSymbolAddress(&p_tk,  g_tk);
    cudaGetSymbolAddress(&p_tv,  g_tv);
    cudaGetSymbolAddress(&p_tpe, g_tpe);
    cudaGetSymbolAddress(&p_tqw, g_tqw);
    cudaGetSymbolAddress(&p_tkw, g_tkw);
    cudaGetSymbolAddress(&p_tvw, g_tvw);
    cudaGetSymbolAddress(&p_trk, g_trk);
    cudaGetSymbolAddress(&p_tpw, g_tpw);

    const dim3 blk(256);

    // ---- pass 1: tf32-round all GEMM operands
    R9 r;
    r.in[0]=q;   r.out[0]=(float*)p_tq;  r.n[0]=BB*LL*DD;
    r.in[1]=k;   r.out[1]=(float*)p_tk;  r.n[1]=BB*LL*DD;
    r.in[2]=v;   r.out[2]=(float*)p_tv;  r.n[2]=BB*LL*DD;
    r.in[3]=pe;  r.out[3]=(float*)p_tpe; r.n[3]=RR*DD;
    r.in[4]=q_w; r.out[4]=(float*)p_tqw; r.n[4]=DD*NN*HH;
    r.in[5]=k_w; r.out[5]=(float*)p_tkw; r.n[5]=DD*NN*HH;
    r.in[6]=v_w; r.out[6]=(float*)p_tvw; r.n[6]=DD*NN*HH;
    r.in[7]=rk;  r.out[7]=(float*)p_trk; r.n[7]=NN*DD*HH;
    r.in[8]=pw;  r.out[8]=(float*)p_tpw; r.n[8]=NN*HH*DD;
    roundk<<<dim3(1024, 9), blk>>>(r);

    // ---- pass 2: q/k/v projections + rpos in ONE launch (grid.z = 0..3)
    cudaFuncSetAttribute(gemm_qkvr, cudaFuncAttributeMaxDynamicSharedMemorySize, GEMM_SMEM);
    cudaFuncSetAttribute(gemm_post, cudaFuncAttributeMaxDynamicSharedMemorySize, GEMM_SMEM);

    GemmArgs gq = { (const float*)p_tq,  (const float*)p_tqw, nullptr, nullptr, nullptr };
    GemmArgs gk = { (const float*)p_tk,  (const float*)p_tkw, k_b,     nullptr, nullptr };
    GemmArgs gv = { (const float*)p_tv,  (const float*)p_tvw, v_b,     nullptr, nullptr };
    GemmArgs gr = { (const float*)p_tpe, (const float*)p_trk, nullptr, nullptr, nullptr };
    gemm_qkvr<<<dim3(8, 32, 4), blk, GEMM_SMEM>>>(gq, gk, gv, gr);

    // ---- pass 2b: c_u = (rrb-rwb).r  (depends on g_rb)
    cu_kernel<<<dim3(128), blk>>>(rwb, rrb);

    // ---- pass 3: fused attention (double-buffered staging)
    cudaFuncSetAttribute(attn_mma, cudaFuncAttributeMaxDynamicSharedMemorySize, ATT_SMEM);
    attn_mma<<<dim3(LL/64, BB*NN), blk, ATT_SMEM>>>(pad, rwb);

    // ---- pass 4: post GEMM (+bias +residual)
    GemmArgs gp = { (const float*)p_o, (const float*)p_tpw, pb, q, (float*)p_x };
    gemm_post<<<dim3(8, 32, 1), blk, GEMM_SMEM>>>(gp);

    // ---- pass 5: layernorm
    ln_kernel<<<BB*LL, blk>>>(lng, lnb, (float*)d_out);
}

// round 16
// speedup vs baseline: 1.3252x; 1.3252x over previous
#include <cuda_runtime.h>
#include <cuda_fp16.h>
#include <math.h>
#include <stdint.h>

#define BB 4
#define LL 1024
#define DD 1024
#define NN 16
#define HH 64
#define RR 2048

// ---------------- scratch ----------------------------------------------------
__device__ float g_qh[BB*NN*LL*HH];   // fp32 (feeds attn QW build)
__device__ float g_cu[NN*RR + 128];
__device__ float g_x [BB*LL*DD];

__device__ __half g_oh [BB*NN*LL*HH]; // attention output (fp16, POST A operand)
__device__ __half g_khb[BB*NN*LL*HH];
__device__ __half g_vhb[BB*NN*LL*HH];
__device__ __half g_rb [NN*RR*HH];

// fp16 GEMM operands (written by roundk)
__device__ __half g_hq [BB*LL*DD];
__device__ __half g_hk [BB*LL*DD];
__device__ __half g_hv [BB*LL*DD];
__device__ __half g_hpe[RR*DD];
__device__ __half g_hqw[DD*NN*HH];
__device__ __half g_hkw[DD*NN*HH];
__device__ __half g_hvw[DD*NN*HH];
__device__ __half g_hrk[NN*DD*HH];
__device__ __half g_hpw[NN*HH*DD];

// ---------------- helpers ----------------------------------------------------
__device__ __forceinline__ float ex2f(float x) {
    float y; asm("ex2.approx.ftz.f32 %0, %1;" : "=f"(y) : "f"(x)); return y;
}
// pack (lo=a, hi=b) into f16x2
__device__ __forceinline__ uint32_t hf2(float a, float b) {
    uint32_t r; asm("cvt.rn.f16x2.f32 %0, %1, %2;" : "=r"(r) : "f"(b), "f"(a)); return r;
}
__device__ __forceinline__ void cpa16(uint32_t dst, const void* src) {
    asm volatile("cp.async.cg.shared.global [%0], [%1], 16;\n" :: "r"(dst), "l"(src));
}
__device__ __forceinline__ void mma_f16(float* d, const uint32_t* a, const uint32_t* b) {
    asm volatile(
        "mma.sync.aligned.m16n8k16.row.col.f32.f16.f16.f32 "
        "{%0,%1,%2,%3}, {%4,%5,%6,%7}, {%8,%9}, {%0,%1,%2,%3};\n"
        : "+f"(d[0]), "+f"(d[1]), "+f"(d[2]), "+f"(d[3])
        : "r"(a[0]), "r"(a[1]), "r"(a[2]), "r"(a[3]), "r"(b[0]), "r"(b[1]));
}
__device__ __forceinline__ void ldsm_x4(uint32_t& r0, uint32_t& r1, uint32_t& r2, uint32_t& r3, uint32_t addr) {
    asm volatile("ldmatrix.sync.aligned.m8n8.x4.shared.b16 {%0,%1,%2,%3}, [%4];"
                 : "=r"(r0), "=r"(r1), "=r"(r2), "=r"(r3) : "r"(addr));
}
__device__ __forceinline__ void ldsm_x4t(uint32_t& r0, uint32_t& r1, uint32_t& r2, uint32_t& r3, uint32_t addr) {
    asm volatile("ldmatrix.sync.aligned.m8n8.x4.trans.shared.b16 {%0,%1,%2,%3}, [%4];"
                 : "=r"(r0), "=r"(r1), "=r"(r2), "=r"(r3) : "r"(addr));
}

// ---------------- fp16 rounding pass (all GEMM operands) ---------------------
struct R9 { const float* in[9]; __half* out[9]; int n[9]; };

__global__ __launch_bounds__(256)
void roundk(R9 r)
{
    const int seg = blockIdx.y;
    const float* in = r.in[seg];
    __half*     out = r.out[seg];
    const int n = r.n[seg];
    for (int i = (blockIdx.x*256 + threadIdx.x)*4; i < n; i += gridDim.x*256*4) {
        float4 v = *reinterpret_cast<const float4*>(in + i);
        uint2 p = make_uint2(hf2(v.x, v.y), hf2(v.z, v.w));
        *reinterpret_cast<uint2*>(out + i) = p;
    }
}

// ---------------- c_u precompute ---------------------------------------------
__global__ __launch_bounds__(256)
void cu_kernel(const float* __restrict__ rwb, const float* __restrict__ rrb)
{
    const int idx = blockIdx.x*256 + threadIdx.x;
    const int n = idx >> 11, j = idx & 2047;
    const __half* rr = g_rb + ((long)n*RR + j)*HH;
    const float* dw = rwb + n*64;
    const float* dr = rrb + n*64;
    float acc = 0.f;
    #pragma unroll
    for (int h = 0; h < 64; h++)
        acc += (dr[h]-dw[h]) * __half2float(rr[h]);
    g_cu[idx] = acc;
}

// ---------------- fp16 ldmatrix GEMM (128x128 tile, K=1024, 2-stage) --------
// A staged [128 rows][32 k] fp16, row stride 80B (phase-distinct for ldsm_x4).
// B staged [32 k][128 n] fp16, row stride 272B (phase-distinct for ldsm_x4t).
struct GemmArgs {
    const __half* A;
    const __half* W;
    const float*  bias;
    const float*  resid;
};

#define GA_STR 80
#define GB_STR 272
#define GA_BYTES (128*GA_STR)     // 10240
#define GB_BYTES (32*GB_STR)      // 8704
#define GSTAGE   (GA_BYTES + GB_BYTES)
#define GEMM_SMEM (2*GSTAGE)      // 37888

// mode: 0 q, 1 k, 2 v, 3 rpos, 4 post
__device__ __forceinline__ void gstage(
    const __half* __restrict__ A, const __half* __restrict__ W, int mode,
    uint32_t buf, int row0, int col0, int k0, int tid)
{
    #pragma unroll
    for (int i = 0; i < 4; i++) {
        const int idx = tid + i*256;          // 0..1023
        if (idx < 512) {                      // A: 128 rows x 4 chunks
            const int r = idx >> 2, q = (idx & 3)*8;
            const __half* src;
            if (mode == 4) {
                const int row = row0 + r, k = k0 + q;
                src = A + (long)(row >> 10)*(NN*LL*HH) + (long)(k >> 6)*(LL*HH)
                        + (long)(row & 1023)*HH + (k & 63);
            } else {
                src = A + (long)(row0 + r)*1024 + k0 + q;
            }
            cpa16(buf + r*GA_STR + (q >> 3)*16, src);
        } else {                              // B: 32 k x 16 chunks
            const int id2 = idx - 512;
            const int kk = id2 >> 4, q = (id2 & 15)*8;
            const __half* src;
            if (mode == 3) {
                const int col = col0 + q;
                src = W + (long)(col >> 6)*(DD*HH) + (long)(k0 + kk)*HH + (col & 63);
            } else {
                src = W + (long)(k0 + kk)*1024 + col0 + q;
            }
            cpa16(buf + GA_BYTES + kk*GB_STR + (q >> 3)*16, src);
        }
    }
    asm volatile("cp.async.commit_group;\n");
}

template<bool POST>
__global__ __launch_bounds__(256, 2)
void gemm_fp16(GemmArgs g0, GemmArgs g1, GemmArgs g2, GemmArgs g3)
{
    const int z = POST ? 4 : blockIdx.z;
    if (!POST && z == 3 && blockIdx.y >= 16) return;
    const GemmArgs ga = POST ? g0 : ((z==0)?g0 : (z==1)?g1 : (z==2)?g2 : g3);

    extern __shared__ char sm[];
    const uint32_t s0 = (uint32_t)__cvta_generic_to_shared(sm);
    const int tid  = threadIdx.x;
    const int lane = tid & 31;
    const int w    = tid >> 5;
    const int wm   = w & 1;
    const int wn   = w >> 1;
    const int row0 = blockIdx.y * 128;
    const int col0 = blockIdx.x * 128;

    const int gA   = lane >> 3;
    const int laneRow = (gA & 1)*8 + (lane & 7);  // A ldsm row within m16
    const int colA    = (gA >> 1)*8;              // A ldsm k offset
    const int tsel = (lane & 15);                 // B x4t k row
    const int csel = ((lane & 16) >> 1);          // B x4t col offset

    float acc[4][4][4];
    #pragma unroll
    for (int i = 0; i < 4; i++)
        #pragma unroll
        for (int j = 0; j < 4; j++)
            #pragma unroll
            for (int q = 0; q < 4; q++) acc[i][j][q] = 0.f;

    gstage(ga.A, ga.W, z, s0, row0, col0, 0, tid);

    const int NIT = 1024/32;
    for (int it = 0; it < NIT; it++) {
        const uint32_t bs = s0 + (uint32_t)((it & 1)*GSTAGE);
        if (it + 1 < NIT) {
            gstage(ga.A, ga.W, z, s0 + (uint32_t)(((it+1) & 1)*GSTAGE),
                   row0, col0, (it+1)*32, tid);
            asm volatile("cp.async.wait_group 1;\n");
        } else {
            asm volatile("cp.async.wait_group 0;\n");
        }
        __syncthreads();

        #pragma unroll
        for (int k0h = 0; k0h < 32; k0h += 16) {
            uint32_t af[4][4], bfr[2][4];
            #pragma unroll
            for (int im = 0; im < 4; im++)
                ldsm_x4(af[im][0], af[im][1], af[im][2], af[im][3],
                        bs + (wm*64 + im*16 + laneRow)*GA_STR + (k0h + colA)*2);
            #pragma unroll
            for (int p = 0; p < 2; p++)
                ldsm_x4t(bfr[p][0], bfr[p][1], bfr[p][2], bfr[p][3],
                         bs + GA_BYTES + (k0h + tsel)*GB_STR + (wn*32 + p*16 + csel)*2);
            #pragma unroll
            for (int im = 0; im < 4; im++)
                #pragma unroll
                for (int jn = 0; jn < 4; jn++)
                    mma_f16(acc[im][jn], af[im], &bfr[jn >> 1][(jn & 1)*2]);
        }
        __syncthreads();
    }

    // ---- epilogue (same fragment layout as before)
    const int fr = lane >> 2;
    const int fc = lane & 3;
    #pragma unroll
    for (int jn = 0; jn < 4; jn++) {
        const int colp = col0 + wn*32 + jn*8 + fc*2;
        float b0 = 0.f, b1 = 0.f;
        if ((z == 1 || z == 2 || z == 4) && ga.bias != nullptr) {
            b0 = ga.bias[colp]; b1 = ga.bias[colp + 1];
        }
        #pragma unroll
        for (int im = 0; im < 4; im++) {
            #pragma unroll
            for (int half = 0; half < 2; half++) {
                const int row = row0 + wm*64 + im*16 + fr + half*8;
                float v0 = acc[im][jn][half*2 + 0] + b0;
                float v1 = acc[im][jn][half*2 + 1] + b1;
                if (z == 4) {
                    long o = (long)row*1024 + colp;
                    float2 rr = *reinterpret_cast<const float2*>(ga.resid + o);
                    *reinterpret_cast<float2*>(g_x + o) = make_float2(v0 + rr.x, v1 + rr.y);
                } else if (z == 3) {
                    long o = (long)(colp >> 6)*(RR*HH) + (long)row*HH + (colp & 63);
                    *reinterpret_cast<uint32_t*>(g_rb + o) = hf2(v0, v1);
                } else {
                    long o = (long)((row >> 10)*NN + (colp >> 6))*(LL*HH)
                           + (long)(row & 1023)*HH + (colp & 63);
                    if (z == 0)
                        *reinterpret_cast<float2*>(g_qh + o) = make_float2(v0, v1);
                    else if (z == 1)
                        *reinterpret_cast<uint32_t*>(g_khb + o) = hf2(v0, v1);
                    else
                        *reinterpret_cast<uint32_t*>(g_vhb + o) = hf2(v0, v1);
                }
            }
        }
    }
}

// ---------------- fused attention: fp16 mma + ldmatrix, double-buffered -----
#define QW_OFF   0
#define KT_OFF   9216
#define RB_OFF   18432
#define VS_OFF   36864
#define BUF_STR  36864
#define G2_OFF   82944
#define PS_OFF   82944
#define MK_OFF   99840
#define RM_OFF   100096
#define RS_OFF   100608
#define CU_OFF   101120
#define ATT_SMEM 101632
#define SC_LOG2 0.18033688011112042f
#define MASK_LOG2 -1442695.04f

__global__ __launch_bounds__(256, 2)
void attn_mma(const int* __restrict__ padding,
              const float* __restrict__ rwb)
{
    extern __shared__ char smB[];
    const uint32_t s0 = (uint32_t)__cvta_generic_to_shared(smB);
    __half* G2h  = reinterpret_cast<__half*>(smB + G2_OFF);
    float* maskv = reinterpret_cast<float*>(smB + MK_OFF);
    float* rmaxs = reinterpret_cast<float*>(smB + RM_OFF);
    float* rsums = reinterpret_cast<float*>(smB + RS_OFF);
    float* cu_s  = reinterpret_cast<float*>(smB + CU_OFF);

    const int tid  = threadIdx.x;
    const int lane = tid & 31;
    const int w    = tid >> 5;
    const int wr   = w >> 1;
    const int wc   = w & 1;
    const int fr   = lane >> 2;
    const int fc   = lane & 3;
    const int bn   = blockIdx.y;
    const int l0   = blockIdx.x * 64;
    const int b    = bn >> 4;
    const int n    = bn & 15;

    const float* qh = g_qh + (long)bn * (LL*HH);
    const __half* khb = g_khb + (long)bn * (LL*HH);
    const __half* vhb = g_vhb + (long)bn * (LL*HH);
    const __half* rbp = g_rb  + (long)n  * (RR*HH);
    const float* cp = g_cu + (long)n  * RR;
    __half*      op = g_oh + (long)bn * (LL*HH);

    #pragma unroll
    for (int i = 0; i < 4; i++) {
        const int idx = tid + i*256;
        const int l = idx >> 4, hc = (idx & 15)*4;
        float4 v = *reinterpret_cast<const float4*>(qh + (long)(l0 + l)*64 + hc);
        float bw0 = rwb[n*64 + hc + 0], bw1 = rwb[n*64 + hc + 1];
        float bw2 = rwb[n*64 + hc + 2], bw3 = rwb[n*64 + hc + 3];
        *reinterpret_cast<uint2*>(smB + QW_OFF + l*144 + hc*2) =
            make_uint2(hf2(v.x + bw0, v.y + bw1), hf2(v.z + bw2, v.w + bw3));
    }
    if (tid < 36) {
        reinterpret_cast<float*>(smB + RB_OFF + 127*144)[tid] = 0.f;
        reinterpret_cast<float*>(smB + RB_OFF + BUF_STR + 127*144)[tid] = 0.f;
    }

    {
        const int jmin0 = LL - l0 - 63;
        #pragma unroll
        for (int i = 0; i < 2; i++) {
            const int idx = tid + i*256;
            const int row = idx >> 3, c = (idx & 7)*8;
            cpa16(s0 + KT_OFF + row*144 + c*2, khb + (long)row*64 + c);
        }
        #pragma unroll
        for (int i = 0; i < 4; i++) {
            const int idx = tid + i*256;
            if (idx < 1016) {
                const int row = idx >> 3, c = (idx & 7)*8;
                cpa16(s0 + RB_OFF + row*144 + c*2, rbp + (long)(jmin0 + row)*64 + c);
            }
        }
        #pragma unroll
        for (int i = 0; i < 2; i++) {
            const int idx = tid + i*256;
            const int row = idx >> 3, c = (idx & 7)*8;
            cpa16(s0 + VS_OFF + row*144 + c*2, vhb + (long)row*64 + c);
        }
        asm volatile("cp.async.commit_group;\n");
        if (tid < 64)
            maskv[tid] = (padding[b*LL + tid] != 0) ? MASK_LOG2 : 0.0f;
        if (tid < 128)
            cu_s[tid] = cp[jmin0 + tid];
    }

    const int gA   = lane >> 3;
    const int rA   = lane & 7;
    const int rowA = wr*16 + (gA & 1)*8 + rA;
    const int colA = (gA >> 1)*8;
    const uint32_t aQW = s0 + QW_OFF + rowA*144 + colA*2;
    const uint32_t aPS = s0 + PS_OFF + rowA*144 + colA*2;
    const int nsel = (lane & 7) + ((lane & 16) >> 1);
    const int ksel = (lane & 8);
    const int tsel = (lane & 15);
    const int csel = ((lane & 16) >> 1);

    float O[4][4];
    float mi[2], li[2];
    #pragma unroll
    for (int jn = 0; jn < 4; jn++)
        #pragma unroll
        for (int q = 0; q < 4; q++) O[jn][q] = 0.f;
    mi[0] = mi[1] = -1e30f;
    li[0] = li[1] = 0.f;

    for (int t = 0; t < 16; t++) {
        const int m0  = t*64;
        const uint32_t bo  = (uint32_t)((t & 1) * BUF_STR);
        const uint32_t bon = (uint32_t)(((t + 1) & 1) * BUF_STR);
        const int jmin = LL + m0 - l0 - 63;

        __syncthreads();
        asm volatile("cp.async.wait_group 0;\n");

        if (t + 1 < 16) {
            const int m0n = m0 + 64;
            #pragma unroll
            for (int i = 0; i < 2; i++) {
                const int idx = tid + i*256;
                const int row = idx >> 3, c = (idx & 7)*8;
                cpa16(s0 + KT_OFF + bon + row*144 + c*2, khb + (long)(m0n + row)*64 + c);
            }
            #pragma unroll
            for (int i = 0; i < 4; i++) {
                const int idx = tid + i*256;
                if (idx < 1016) {
                    const int row = idx >> 3, c = (idx & 7)*8;
                    cpa16(s0 + RB_OFF + bon + row*144 + c*2,
                          rbp + (long)(jmin + 64 + row)*64 + c);
                }
            }
            #pragma unroll
            for (int i = 0; i < 2; i++) {
                const int idx = tid + i*256;
                const int row = idx >> 3, c = (idx & 7)*8;
                cpa16(s0 + VS_OFF + bon + row*144 + c*2, vhb + (long)(m0n + row)*64 + c);
            }
            asm volatile("cp.async.commit_group;\n");
        }

        float pm = 0.f, pc = 0.f;
        if (t + 1 < 16) {
            if (tid < 64)
                pm = (padding[b*LL + m0 + 64 + tid] != 0) ? MASK_LOG2 : 0.0f;
            if (tid < 128)
                pc = cp[jmin + 64 + tid];
        }

        __syncthreads();

        float s1[4][4], g2[4][4];
        #pragma unroll
        for (int jn = 0; jn < 4; jn++)
            #pragma unroll
            for (int q = 0; q < 4; q++) { s1[jn][q] = 0.f; g2[jn][q] = 0.f; }
        #pragma unroll
        for (int k0 = 0; k0 < 64; k0 += 16) {
            uint32_t a[4];
            ldsm_x4(a[0], a[1], a[2], a[3], aQW + k0*2);
            #pragma unroll
            for (int p = 0; p < 2; p++) {
                uint32_t b4[4];
                ldsm_x4(b4[0], b4[1], b4[2], b4[3],
                        s0 + KT_OFF + bo + (wc*32 + p*16 + nsel)*144 + (k0 + ksel)*2);
                mma_f16(s1[p*2],   a, b4);
                mma_f16(s1[p*2+1], a, b4 + 2);
            }
            #pragma unroll
            for (int p = 0; p < 2; p++) {
                uint32_t b4[4];
                ldsm_x4(b4[0], b4[1], b4[2], b4[3],
                        s0 + RB_OFF + bo + (wc*64 + p*16 + nsel)*144 + (k0 + ksel)*2);
                mma_f16(g2[p*2],   a, b4);
                mma_f16(g2[p*2+1], a, b4 + 2);
            }
        }
        {
            const int lb = (wr*16 + fr)*132;
            #pragma unroll
            for (int jn = 0; jn < 4; jn++) {
                const int ub = wc*64 + jn*8 + fc*2;
                float2 cc = *reinterpret_cast<const float2*>(&cu_s[ub]);
                *reinterpret_cast<uint32_t*>(smB + G2_OFF + (lb + ub)*2) =
                    hf2(g2[jn][0] + cc.x, g2[jn][1] + cc.y);
                *reinterpret_cast<uint32_t*>(smB + G2_OFF + (lb + 8*132 + ub)*2) =
                    hf2(g2[jn][2] + cc.x, g2[jn][3] + cc.y);
            }
        }
        #pragma unroll
        for (int jn = 0; jn < 4; jn++)
            #pragma unroll
            for (int q = 0; q < 4; q++) g2[jn][q] = 0.f;
        #pragma unroll
        for (int k0 = 0; k0 < 64; k0 += 16) {
            uint32_t a[4];
            ldsm_x4(a[0], a[1], a[2], a[3], aQW + k0*2);
            #pragma unroll
            for (int p = 0; p < 2; p++) {
                uint32_t b4[4];
                ldsm_x4(b4[0], b4[1], b4[2], b4[3],
                        s0 + RB_OFF + bo + (wc*64 + 32 + p*16 + nsel)*144 + (k0 + ksel)*2);
                mma_f16(g2[p*2],   a, b4);
                mma_f16(g2[p*2+1], a, b4 + 2);
            }
        }
        {
            const int lb = (wr*16 + fr)*132;
            #pragma unroll
            for (int jn = 0; jn < 4; jn++) {
                const int ub = wc*64 + 32 + jn*8 + fc*2;
                float2 cc = *reinterpret_cast<const float2*>(&cu_s[ub]);
                *reinterpret_cast<uint32_t*>(smB + G2_OFF + (lb + ub)*2) =
                    hf2(g2[jn][0] + cc.x, g2[jn][1] + cc.y);
                *reinterpret_cast<uint32_t*>(smB + G2_OFF + (lb + 8*132 + ub)*2) =
                    hf2(g2[jn][2] + cc.x, g2[jn][3] + cc.y);
            }
        }
        __syncthreads();

        float sv[4][4];
        float rmx[2] = {-1e30f, -1e30f};
        #pragma unroll
        for (int jn = 0; jn < 4; jn++) {
            #pragma unroll
            for (int q = 0; q < 4; q++) {
                const int ll = wr*16 + fr + (q >> 1)*8;
                const int mc = wc*32 + jn*8 + fc*2 + (q & 1);
                const int u  = mc - ll + 63;
                float x = (s1[jn][q] + __half2float(G2h[ll*132 + u])) * SC_LOG2
                        + maskv[mc];
                sv[jn][q] = x;
                rmx[q >> 1] = fmaxf(rmx[q >> 1], x);
            }
        }
        #pragma unroll
        for (int r = 0; r < 2; r++) {
            rmx[r] = fmaxf(rmx[r], __shfl_xor_sync(0xffffffffu, rmx[r], 1));
            rmx[r] = fmaxf(rmx[r], __shfl_xor_sync(0xffffffffu, rmx[r], 2));
        }
        if (fc == 0) {
            rmaxs[wc*64 + wr*16 + fr]     = rmx[0];
            rmaxs[wc*64 + wr*16 + fr + 8] = rmx[1];
        }
        __syncthreads();

        if (t + 1 < 16) {
            if (tid < 64)  maskv[tid] = pm;
            if (tid < 128) cu_s[tid]  = pc;
        }

        float nm[2], al[2], psum[2];
        #pragma unroll
        for (int r = 0; r < 2; r++) {
            const int row = wr*16 + fr + r*8;
            const float tm = fmaxf(rmaxs[row], rmaxs[64 + row]);
            nm[r] = fmaxf(mi[r], tm);
            al[r] = ex2f(mi[r] - nm[r]);
            mi[r] = nm[r];
            psum[r] = 0.f;
        }
        #pragma unroll
        for (int jn = 0; jn < 4; jn++) {
            #pragma unroll
            for (int r = 0; r < 2; r++) {
                float p0 = ex2f(sv[jn][r*2 + 0] - nm[r]);
                float p1 = ex2f(sv[jn][r*2 + 1] - nm[r]);
                psum[r] += p0 + p1;
                const int ll = wr*16 + fr + r*8;
                const int mc = wc*32 + jn*8 + fc*2;
                *reinterpret_cast<uint32_t*>(smB + PS_OFF + ll*144 + mc*2) = hf2(p0, p1);
            }
        }
        #pragma unroll
        for (int r = 0; r < 2; r++) {
            psum[r] += __shfl_xor_sync(0xffffffffu, psum[r], 1);
            psum[r] += __shfl_xor_sync(0xffffffffu, psum[r], 2);
        }
        if (fc == 0) {
            rsums[wc*64 + wr*16 + fr]     = psum[0];
            rsums[wc*64 + wr*16 + fr + 8] = psum[1];
        }
        __syncthreads();

        #pragma unroll
        for (int r = 0; r < 2; r++) {
            const int row = wr*16 + fr + r*8;
            li[r] = li[r]*al[r] + (rsums[row] + rsums[64 + row]);
        }
        #pragma unroll
        for (int jn = 0; jn < 4; jn++) {
            O[jn][0] *= al[0]; O[jn][1] *= al[0];
            O[jn][2] *= al[1]; O[jn][3] *= al[1];
        }
        #pragma unroll
        for (int k0 = 0; k0 < 64; k0 += 16) {
            uint32_t a[4];
            ldsm_x4(a[0], a[1], a[2], a[3], aPS + k0*2);
            #pragma unroll
            for (int p = 0; p < 2; p++) {
                uint32_t b4[4];
                ldsm_x4t(b4[0], b4[1], b4[2], b4[3],
                         s0 + VS_OFF + bo + (k0 + tsel)*144 + (wc*32 + p*16 + csel)*2);
                mma_f16(O[p*2],   a, b4);
                mma_f16(O[p*2+1], a, b4 + 2);
            }
        }
    }

    const float inv0 = 1.0f / li[0];
    const float inv1 = 1.0f / li[1];
    #pragma unroll
    for (int jn = 0; jn < 4; jn++) {
        const int col = wc*32 + jn*8 + fc*2;
        const int lr0 = l0 + wr*16 + fr;
        *reinterpret_cast<uint32_t*>(op + (long)lr0*64 + col) =
            hf2(O[jn][0]*inv0, O[jn][1]*inv0);
        *reinterpret_cast<uint32_t*>(op + (long)(lr0 + 8)*64 + col) =
            hf2(O[jn][2]*inv1, O[jn][3]*inv1);
    }
}

// ---------------- layernorm --------------------------------------------------
__global__ __launch_bounds__(256)
void ln_kernel(const float* __restrict__ lng, const float* __restrict__ lnb,
               float* __restrict__ out)
{
    __shared__ float part[8];
    __shared__ float bcast;
    const int row = blockIdx.x;
    const int tid = threadIdx.x;
    const int lane = tid & 31;
    const int wid = tid >> 5;
    const float* x = g_x + (long)row * DD;

    float4 v = reinterpret_cast<const float4*>(x)[tid];
    float s = v.x + v.y + v.z + v.w;
    #pragma unroll
    for (int off = 16; off > 0; off >>= 1)
        s += __shfl_xor_sync(0xffffffffu, s, off);
    if (lane == 0) part[wid] = s;
    __syncthreads();
    if (tid == 0) {
        float t = 0.f;
        #pragma unroll
        for (int i = 0; i < 8; i++) t += part[i];
        bcast = t * (1.f / DD);
    }
    __syncthreads();
    const float mu = bcast;

    float dx = v.x - mu, dy = v.y - mu, dz = v.z - mu, dw = v.w - mu;
    float vs = dx*dx + dy*dy + dz*dz + dw*dw;
    #pragma unroll
    for (int off = 16; off > 0; off >>= 1)
        vs += __shfl_xor_sync(0xffffffffu, vs, off);
    if (lane == 0) part[wid] = vs;
    __syncthreads();
    if (tid == 0) {
        float t = 0.f;
        #pragma unroll
        for (int i = 0; i < 8; i++) t += part[i];
        bcast = rsqrtf(t * (1.f / DD) + 1e-5f);
    }
    __syncthreads();
    const float inv = bcast;

    float4 g = reinterpret_cast<const float4*>(lng)[tid];
    float4 be = reinterpret_cast<const float4*>(lnb)[tid];
    float4 o;
    o.x = dx * inv * g.x + be.x;
    o.y = dy * inv * g.y + be.y;
    o.z = dz * inv * g.z + be.z;
    o.w = dw * inv * g.w + be.w;
    reinterpret_cast<float4*>(out + (long)row*DD)[tid] = o;
}

// ---------------- launcher ---------------------------------------------------
extern "C" void kernel_launch(void* const* d_in, const int* in_sizes, int n_in,
                              void* d_out, int out_size)
{
    const float* q   = (const float*)d_in[0];
    const float* k   = (const float*)d_in[1];
    const float* v   = (const float*)d_in[2];
    const float* pe  = (const float*)d_in[3];
    const int*   pad = (const int*)d_in[4];
    const float* q_w = (const float*)d_in[5];
    const float* k_w = (const float*)d_in[6];
    const float* k_b = (const float*)d_in[7];
    const float* v_w = (const float*)d_in[8];
    const float* v_b = (const float*)d_in[9];
    const float* rwb = (const float*)d_in[10];
    const float* rrb = (const float*)d_in[11];
    const float* rk  = (const float*)d_in[12];
    const float* pw  = (const float*)d_in[13];
    const float* pb  = (const float*)d_in[14];
    const float* lng = (const float*)d_in[15];
    const float* lnb = (const float*)d_in[16];

    void *p_oh, *p_hq, *p_hk, *p_hv, *p_hpe, *p_hqw, *p_hkw, *p_hvw, *p_hrk, *p_hpw;
    cudaGetSymbolAddress(&p_oh,  g_oh);
    cudaGetSymbolAddress(&p_hq,  g_hq);
    cudaGetSymbolAddress(&p_hk,  g_hk);
    cudaGetSymbolAddress(&p_hv,  g_hv);
    cudaGetSymbolAddress(&p_hpe, g_hpe);
    cudaGetSymbolAddress(&p_hqw, g_hqw);
    cudaGetSymbolAddress(&p_hkw, g_hkw);
    cudaGetSymbolAddress(&p_hvw, g_hvw);
    cudaGetSymbolAddress(&p_hrk, g_hrk);
    cudaGetSymbolAddress(&p_hpw, g_hpw);

    const dim3 blk(256);

    // pass 1: fp16-round all GEMM operands
    R9 r;
    r.in[0]=q;   r.out[0]=(__half*)p_hq;  r.n[0]=BB*LL*DD;
    r.in[1]=k;   r.out[1]=(__half*)p_hk;  r.n[1]=BB*LL*DD;
    r.in[2]=v;   r.out[2]=(__half*)p_hv;  r.n[2]=BB*LL*DD;
    r.in[3]=pe;  r.out[3]=(__half*)p_hpe; r.n[3]=RR*DD;
    r.in[4]=q_w; r.out[4]=(__half*)p_hqw; r.n[4]=DD*NN*HH;
    r.in[5]=k_w; r.out[5]=(__half*)p_hkw; r.n[5]=DD*NN*HH;
    r.in[6]=v_w; r.out[6]=(__half*)p_hvw; r.n[6]=DD*NN*HH;
    r.in[7]=rk;  r.out[7]=(__half*)p_hrk; r.n[7]=NN*DD*HH;
    r.in[8]=pw;  r.out[8]=(__half*)p_hpw; r.n[8]=NN*HH*DD;
    roundk<<<dim3(1024, 9), blk>>>(r);

    // pass 2: q/k/v/rpos GEMMs (fp16 ldmatrix, one launch)
    cudaFuncSetAttribute(gemm_fp16<false>, cudaFuncAttributeMaxDynamicSharedMemorySize, GEMM_SMEM);
    cudaFuncSetAttribute(gemm_fp16<true>,  cudaFuncAttributeMaxDynamicSharedMemorySize, GEMM_SMEM);

    GemmArgs gq = { (const __half*)p_hq,  (const __half*)p_hqw, nullptr, nullptr };
    GemmArgs gk = { (const __half*)p_hk,  (const __half*)p_hkw, k_b,     nullptr };
    GemmArgs gv = { (const __half*)p_hv,  (const __half*)p_hvw, v_b,     nullptr };
    GemmArgs gr = { (const __half*)p_hpe, (const __half*)p_hrk, nullptr, nullptr };
    gemm_fp16<false><<<dim3(8, 32, 4), blk, GEMM_SMEM>>>(gq, gk, gv, gr);

    // pass 2b: c_u
    cu_kernel<<<dim3(128), blk>>>(rwb, rrb);

    // pass 3: fused attention (fp16)
    cudaFuncSetAttribute(attn_mma, cudaFuncAttributeMaxDynamicSharedMemorySize, ATT_SMEM);
    attn_mma<<<dim3(LL/64, BB*NN), blk, ATT_SMEM>>>(pad, rwb);

    // pass 4: post GEMM
    GemmArgs gp = { (const __half*)p_oh, (const __half*)p_hpw, pb, q };
    gemm_fp16<true><<<dim3(8, 32, 1), blk, GEMM_SMEM>>>(gp, gp, gp, gp);

    // pass 5: layernorm
    ln_kernel<<<BB*LL, blk>>>(lng, lnb, (float*)d_out);
}